// round 13
// baseline (speedup 1.0000x reference)
#include <cuda_runtime.h>
#include <cstdint>

#define BFc    116
#define HWs    3136
#define NBATCH 64
#define CTOT   232
#define EPSc   1e-5f
#define TTILE  7          // pixel tiles per block
#define NT     64         // pixels per tile

// ---------------- scratch ----------------
__device__ float g_h1[(size_t)NBATCH * BFc * HWs];
__device__ float g_h2[(size_t)NBATCH * BFc * HWs];
__device__ float g_wt1[128 * 128];
__device__ float g_wt2[128 * 128];
__device__ float g_sh1[128];
__device__ float g_sh2[128];

// ---------------- helpers ----------------
__device__ __forceinline__ float tf32r(float x) {
    uint32_t u;
    asm("cvt.rna.tf32.f32 %0, %1;" : "=r"(u) : "f"(x));
    return __uint_as_float(u);
}
__device__ __forceinline__ uint32_t smem_u32(const void* p) {
    uint32_t a;
    asm("{ .reg .u64 t; cvta.to.shared.u64 t, %1; cvt.u32.u64 %0, t; }" : "=r"(a) : "l"(p));
    return a;
}
__device__ __forceinline__ void cp_async16(uint32_t dst, const void* src) {
    asm volatile("cp.async.cg.shared.global [%0], [%1], 16;" :: "r"(dst), "l"(src));
}
#define CP_COMMIT() asm volatile("cp.async.commit_group;" ::: "memory")

__device__ __forceinline__ void mma_tf32(float* d, const uint32_t* a, const uint32_t* b) {
    asm volatile(
        "mma.sync.aligned.m16n8k8.row.col.f32.tf32.tf32.f32 "
        "{%0,%1,%2,%3}, {%4,%5,%6,%7}, {%8,%9}, {%0,%1,%2,%3};"
        : "+f"(d[0]), "+f"(d[1]), "+f"(d[2]), "+f"(d[3])
        : "r"(a[0]), "r"(a[1]), "r"(a[2]), "r"(a[3]), "r"(b[0]), "r"(b[1]));
}

// ---------------- combined prep ----------------
__global__ void prep_all(const float* __restrict__ w2, const float* __restrict__ bn1g,
                         const float* __restrict__ bn1b, const float* __restrict__ bn1m,
                         const float* __restrict__ bn1v,
                         const float* __restrict__ w3,
                         const float* __restrict__ bn2g, const float* __restrict__ bn2b,
                         const float* __restrict__ bn2m, const float* __restrict__ bn2v,
                         const float* __restrict__ bn3g, const float* __restrict__ bn3b,
                         const float* __restrict__ bn3m, const float* __restrict__ bn3v,
                         float* __restrict__ wt1, float* __restrict__ sh1,
                         float* __restrict__ wt2, float* __restrict__ sh2) {
    if (blockIdx.x < 64) {
        int i = blockIdx.x * 256 + threadIdx.x;
        int o = i >> 7, k = i & 127;
        float val = 0.f;
        if (o < BFc && k < BFc) {
            float s = bn1g[o] * rsqrtf(bn1v[o] + EPSc);
            val = tf32r(w2[o * BFc + k] * s);
        }
        wt1[i] = val;
        if (i < 128) {
            float shv = 0.f;
            if (i < BFc) {
                float s = bn1g[i] * rsqrtf(bn1v[i] + EPSc);
                shv = bn1b[i] - bn1m[i] * s;
            }
            sh1[i] = shv;
        }
        return;
    }
    __shared__ float s2s[BFc], t2s[BFc];
    int tid = threadIdx.x;
    if (tid < BFc) {
        float s2 = bn2g[tid] * rsqrtf(bn2v[tid] + EPSc);
        s2s[tid] = s2;
        t2s[tid] = bn2b[tid] - bn2m[tid] * s2;
    }
    __syncthreads();
    if (tid >= 128) return;
    int o = tid;
    float s3 = 0.f, t3 = 0.f;
    if (o < BFc) {
        s3 = bn3g[o] * rsqrtf(bn3v[o] + EPSc);
        t3 = bn3b[o] - bn3m[o] * s3;
    }
    float acc = 0.f;
    for (int k = 0; k < 128; k++) {
        float val = 0.f;
        if (o < BFc && k < BFc) {
            float wv = w3[o * BFc + k];
            val = tf32r(wv * s3 * s2s[k]);
            acc += wv * t2s[k];
        }
        wt2[o * 128 + k] = val;
    }
    sh2[o] = (o < BFc) ? (t3 + s3 * acc) : 0.f;
}

// ---------------- shuffle-copy: out[b][2k] = x[b][k] ----------------
__global__ void copy_x1_kernel(const float* __restrict__ x, float* __restrict__ out) {
    size_t i = (size_t)blockIdx.x * 256 + threadIdx.x;
    if (i >= (size_t)NBATCH * BFc * (HWs / 4)) return;
    int p4 = (int)(i % (HWs / 4));
    int bk = (int)(i / (HWs / 4));
    int k = bk % BFc;
    int b = bk / BFc;
    const float4* s = (const float4*)(x + ((size_t)b * CTOT + k) * HWs) + p4;
    float4* d = (float4*)(out + ((size_t)b * CTOT + 2 * k) * HWs) + p4;
    *d = *s;
}

// ---------------- split-K chunk-pipelined mma.sync tf32 fused 1x1 conv ----------------
#define WPITCH 124
#define XPITCH 72
#define KA_ROWS 56
#define KB_ROWS 64
#define SM_W   0
#define SM_XA  (128 * WPITCH)
#define SM_XB  (SM_XA + KA_ROWS * XPITCH)
#define SM_S   (SM_XB + KB_ROWS * XPITCH)
#define SMEM_FLOATS (SM_S + 128)

template<bool FIRST>
__global__ __launch_bounds__(256, 2)
void conv1x1_mma(const float* __restrict__ in, const float* __restrict__ wt,
                 const float* __restrict__ shifts, const float* __restrict__ alpha,
                 float* __restrict__ dst, int b0)
{
    extern __shared__ float smem[];
    float* Wsm = smem + SM_W;
    float* Ssm = smem + SM_S;

    const int tid = threadIdx.x;
    const int b = b0 + blockIdx.y;
    const int base = blockIdx.x * (TTILE * NT);

    const float* src_base = FIRST
        ? in + ((size_t)b * CTOT + BFc) * HWs + base
        : in + ((size_t)b * BFc) * HWs + base;

    const uint32_t xa = smem_u32(smem + SM_XA);
    const uint32_t xb = smem_u32(smem + SM_XB);

    for (int i = tid; i < 4 * XPITCH; i += 256)
        smem[SM_XB + 60 * XPITCH + i] = 0.f;

    for (int i = tid; i < KA_ROWS * 16; i += 256) {
        int k = i >> 4, q = i & 15;
        cp_async16(xa + (uint32_t)(k * XPITCH + q * 4) * 4,
                   src_base + (size_t)k * HWs + q * 4);
    }
    CP_COMMIT();
    for (int i = tid; i < 60 * 16; i += 256) {
        int k = i >> 4, q = i & 15;
        cp_async16(xb + (uint32_t)(k * XPITCH + q * 4) * 4,
                   src_base + (size_t)(KA_ROWS + k) * HWs + q * 4);
    }
    CP_COMMIT();

    #pragma unroll 4
    for (int i = tid; i < 128 * 31; i += 256) {
        int o = i / 31, k4 = i % 31;
        float4 v = *(const float4*)(wt + o * 128 + k4 * 4);
        *(float4*)(Wsm + o * WPITCH + k4 * 4) = v;
    }
    if (tid < 128) Ssm[tid] = shifts[tid];

    const int wid = tid >> 5, lane = tid & 31;
    const int gid = lane >> 2, tig = lane & 3;
    const int o0 = (wid >> 1) * 32;
    const int pw = (wid & 1) * 32;
    const float al = __ldg(alpha);

    #pragma unroll 1
    for (int t = 0; t < TTILE; t++) {
        float acc[2][4][4];
        #pragma unroll
        for (int mi = 0; mi < 2; mi++)
            #pragma unroll
            for (int ni = 0; ni < 4; ni++)
                #pragma unroll
                for (int r = 0; r < 4; r++) acc[mi][ni][r] = 0.f;

        asm volatile("cp.async.wait_group 1;" ::: "memory");
        __syncthreads();

        #pragma unroll
        for (int ks = 0; ks < 7; ks++) {
            const int k0 = ks * 8;
            uint32_t a[2][4];
            #pragma unroll
            for (int mi = 0; mi < 2; mi++) {
                const float* wp = Wsm + (o0 + mi * 16 + gid) * WPITCH + k0 + tig;
                a[mi][0] = __float_as_uint(wp[0]);
                a[mi][1] = __float_as_uint(wp[8 * WPITCH]);
                a[mi][2] = __float_as_uint(wp[4]);
                a[mi][3] = __float_as_uint(wp[8 * WPITCH + 4]);
            }
            uint32_t bf[4][2];
            #pragma unroll
            for (int ni = 0; ni < 4; ni++) {
                const float* xp = smem + SM_XA + (k0 + tig) * XPITCH + pw + ni * 8 + gid;
                bf[ni][0] = __float_as_uint(xp[0]);
                bf[ni][1] = __float_as_uint(xp[4 * XPITCH]);
            }
            #pragma unroll
            for (int mi = 0; mi < 2; mi++)
                #pragma unroll
                for (int ni = 0; ni < 4; ni++)
                    mma_tf32(acc[mi][ni], a[mi], bf[ni]);
        }

        __syncthreads();

        if (t + 1 < TTILE) {
            const float* src_t = src_base + (t + 1) * NT;
            for (int i = tid; i < KA_ROWS * 16; i += 256) {
                int k = i >> 4, q = i & 15;
                cp_async16(xa + (uint32_t)(k * XPITCH + q * 4) * 4,
                           src_t + (size_t)k * HWs + q * 4);
            }
            CP_COMMIT();
            asm volatile("cp.async.wait_group 1;" ::: "memory");
        } else {
            asm volatile("cp.async.wait_group 0;" ::: "memory");
        }
        __syncthreads();

        #pragma unroll
        for (int ks = 0; ks < 8; ks++) {
            const int k0 = ks * 8;
            const int wcol = KA_ROWS + k0;
            uint32_t a[2][4];
            #pragma unroll
            for (int mi = 0; mi < 2; mi++) {
                const float* wp = Wsm + (o0 + mi * 16 + gid) * WPITCH + wcol + tig;
                a[mi][0] = __float_as_uint(wp[0]);
                a[mi][1] = __float_as_uint(wp[8 * WPITCH]);
                a[mi][2] = __float_as_uint(wp[4]);
                a[mi][3] = __float_as_uint(wp[8 * WPITCH + 4]);
            }
            uint32_t bf[4][2];
            #pragma unroll
            for (int ni = 0; ni < 4; ni++) {
                const float* xp = smem + SM_XB + (k0 + tig) * XPITCH + pw + ni * 8 + gid;
                bf[ni][0] = __float_as_uint(xp[0]);
                bf[ni][1] = __float_as_uint(xp[4 * XPITCH]);
            }
            #pragma unroll
            for (int mi = 0; mi < 2; mi++)
                #pragma unroll
                for (int ni = 0; ni < 4; ni++)
                    mma_tf32(acc[mi][ni], a[mi], bf[ni]);
        }

        const int p0 = base + t * NT;
        #pragma unroll
        for (int mi = 0; mi < 2; mi++) {
            #pragma unroll
            for (int half = 0; half < 2; half++) {
                const int o = o0 + mi * 16 + gid + half * 8;
                if (o < BFc) {
                    const float sh = Ssm[o];
                    float* dp = FIRST
                        ? dst + ((size_t)b * BFc + o) * HWs + p0
                        : dst + ((size_t)b * CTOT + 2 * o + 1) * HWs + p0;
                    #pragma unroll
                    for (int ni = 0; ni < 4; ni++) {
                        float c0 = acc[mi][ni][half * 2 + 0] + sh;
                        float c1 = acc[mi][ni][half * 2 + 1] + sh;
                        c0 = c0 >= 0.f ? c0 : al * c0;
                        c1 = c1 >= 0.f ? c1 : al * c1;
                        *(float2*)(dp + pw + ni * 8 + 2 * tig) = make_float2(c0, c1);
                    }
                }
            }
        }

        __syncthreads();

        if (t + 1 < TTILE) {
            const float* src_t = src_base + (t + 1) * NT;
            for (int i = tid; i < 60 * 16; i += 256) {
                int k = i >> 4, q = i & 15;
                cp_async16(xb + (uint32_t)(k * XPITCH + q * 4) * 4,
                           src_t + (size_t)(KA_ROWS + k) * HWs + q * 4);
            }
            CP_COMMIT();
        }
    }
}

// ---------------- depthwise 3x3, register-rolling, no smem, no barriers ----------------
__device__ __forceinline__ void dw_load_row(const float* __restrict__ src, int y,
                                            int x0, bool hasL, bool hasR, float* r) {
    if ((unsigned)y < 56u) {
        const float* p = src + y * 56 + x0;
        float4 c = *(const float4*)p;
        r[0] = hasL ? p[-1] : 0.f;
        r[1] = c.x; r[2] = c.y; r[3] = c.z; r[4] = c.w;
        r[5] = hasR ? p[4] : 0.f;
    } else {
        r[0] = r[1] = r[2] = r[3] = r[4] = r[5] = 0.f;
    }
}

__global__ __launch_bounds__(224)
void dwconv_kernel(const float* __restrict__ h1, const float* __restrict__ wdw,
                   float* __restrict__ h2, int plane0)
{
    const int tid = threadIdx.x;
    const int local = tid % 112;
    const int plane = plane0 + blockIdx.x * 2 + tid / 112;
    const int xg = local % 14;
    const int ys = local / 14;
    const int x0 = xg * 4;
    const int y0 = ys * 7;
    const bool hasL = (xg != 0);
    const bool hasR = (xg != 13);

    const int c = plane % BFc;
    const float* src = h1 + (size_t)plane * HWs;
    float* dstp = h2 + (size_t)plane * HWs + x0;

    float w[9];
    #pragma unroll
    for (int j = 0; j < 9; j++) w[j] = __ldg(wdw + c * 9 + j);

    float R[3][6];
    dw_load_row(src, y0 - 1, x0, hasL, hasR, R[0]);
    dw_load_row(src, y0,     x0, hasL, hasR, R[1]);

    #pragma unroll
    for (int j = 0; j < 7; j++) {
        dw_load_row(src, y0 + j + 1, x0, hasL, hasR, R[(j + 2) % 3]);
        const float* T = R[j % 3];
        const float* M = R[(j + 1) % 3];
        const float* B = R[(j + 2) % 3];
        float4 o;
        o.x = w[0]*T[0] + w[1]*T[1] + w[2]*T[2]
            + w[3]*M[0] + w[4]*M[1] + w[5]*M[2]
            + w[6]*B[0] + w[7]*B[1] + w[8]*B[2];
        o.y = w[0]*T[1] + w[1]*T[2] + w[2]*T[3]
            + w[3]*M[1] + w[4]*M[2] + w[5]*M[3]
            + w[6]*B[1] + w[7]*B[2] + w[8]*B[3];
        o.z = w[0]*T[2] + w[1]*T[3] + w[2]*T[4]
            + w[3]*M[2] + w[4]*M[3] + w[5]*M[4]
            + w[6]*B[2] + w[7]*B[3] + w[8]*B[4];
        o.w = w[0]*T[3] + w[1]*T[4] + w[2]*T[5]
            + w[3]*M[3] + w[4]*M[4] + w[5]*M[5]
            + w[6]*B[3] + w[7]*B[4] + w[8]*B[5];
        *(float4*)(dstp + (y0 + j) * 56) = o;
    }
}

// ---------------- launch: staggered two-chain pipeline graph ----------------
extern "C" void kernel_launch(void* const* d_in, const int* in_sizes, int n_in,
                              void* d_out, int out_size) {
    const float* x      = (const float*)d_in[0];
    const float* w2     = (const float*)d_in[1];
    const float* bn1_g  = (const float*)d_in[2];
    const float* bn1_b  = (const float*)d_in[3];
    const float* bn1_m  = (const float*)d_in[4];
    const float* bn1_v  = (const float*)d_in[5];
    const float* alpha1 = (const float*)d_in[6];
    const float* wdw    = (const float*)d_in[7];
    const float* bn2_g  = (const float*)d_in[8];
    const float* bn2_b  = (const float*)d_in[9];
    const float* bn2_m  = (const float*)d_in[10];
    const float* bn2_v  = (const float*)d_in[11];
    const float* w3     = (const float*)d_in[12];
    const float* bn3_g  = (const float*)d_in[13];
    const float* bn3_b  = (const float*)d_in[14];
    const float* bn3_m  = (const float*)d_in[15];
    const float* bn3_v  = (const float*)d_in[16];
    const float* alpha2 = (const float*)d_in[17];
    float* out = (float*)d_out;

    float *h1, *h2, *wt1, *wt2, *sh1, *sh2;
    cudaGetSymbolAddress((void**)&h1,  g_h1);
    cudaGetSymbolAddress((void**)&h2,  g_h2);
    cudaGetSymbolAddress((void**)&wt1, g_wt1);
    cudaGetSymbolAddress((void**)&wt2, g_wt2);
    cudaGetSymbolAddress((void**)&sh1, g_sh1);
    cudaGetSymbolAddress((void**)&sh2, g_sh2);

    const int smem_bytes = SMEM_FLOATS * 4;   // 98560 B -> 2 CTAs/SM
    cudaFuncSetAttribute(conv1x1_mma<true>,
                         cudaFuncAttributeMaxDynamicSharedMemorySize, smem_bytes);
    cudaFuncSetAttribute(conv1x1_mma<false>,
                         cudaFuncAttributeMaxDynamicSharedMemorySize, smem_bytes);

    static bool inited = false;
    static cudaStream_t s1, s2;
    static cudaEvent_t e0, eC1A, e1, e2;
    if (!inited) {
        cudaStreamCreateWithFlags(&s1, cudaStreamNonBlocking);
        cudaStreamCreateWithFlags(&s2, cudaStreamNonBlocking);
        cudaEventCreateWithFlags(&e0,   cudaEventDisableTiming);
        cudaEventCreateWithFlags(&eC1A, cudaEventDisableTiming);
        cudaEventCreateWithFlags(&e1,   cudaEventDisableTiming);
        cudaEventCreateWithFlags(&e2,   cudaEventDisableTiming);
        inited = true;
    }

    const int HB = NBATCH / 2;   // 32 batches per chain

    // fork root
    cudaEventRecord(e0, 0);

    // branch s1: independent shuffle-copy (even output channels), hides under conv1_a
    cudaStreamWaitEvent(s1, e0, 0);
    {
        size_t n4 = (size_t)NBATCH * BFc * (HWs / 4);
        copy_x1_kernel<<<(unsigned)((n4 + 255) / 256), 256, 0, s1>>>(x, out);
    }
    cudaEventRecord(e1, s1);

    // default stream: prep -> chain A, with a stagger event after conv1_a
    prep_all<<<65, 256>>>(w2, bn1_g, bn1_b, bn1_m, bn1_v,
                          w3, bn2_g, bn2_b, bn2_m, bn2_v,
                          bn3_g, bn3_b, bn3_m, bn3_v,
                          wt1, sh1, wt2, sh2);

    conv1x1_mma<true><<<dim3(TTILE, HB), 256, smem_bytes>>>(x, wt1, sh1, alpha1, h1, 0);
    cudaEventRecord(eC1A, 0);

    // chain B staggered one stage behind: conv1_b starts when conv1_a is done,
    // so conv1_b (tensor) overlaps dw_a (memory), conv2_a overlaps dw_b, etc.
    cudaStreamWaitEvent(s2, eC1A, 0);

    dwconv_kernel<<<(HB * BFc) / 2, 224>>>(h1, wdw, h2, 0);
    conv1x1_mma<true><<<dim3(TTILE, HB), 256, smem_bytes, s2>>>(x, wt1, sh1, alpha1, h1, HB);

    conv1x1_mma<false><<<dim3(TTILE, HB), 256, smem_bytes>>>(h2, wt2, sh2, alpha2, out, 0);
    dwconv_kernel<<<(HB * BFc) / 2, 224, 0, s2>>>(h1, wdw, h2, HB * BFc);

    conv1x1_mma<false><<<dim3(TTILE, HB), 256, smem_bytes, s2>>>(h2, wt2, sh2, alpha2, out, HB);
    cudaEventRecord(e2, s2);

    // join both branches back into the default stream
    cudaStreamWaitEvent(0, e1, 0);
    cudaStreamWaitEvent(0, e2, 0);
}

// round 14
// speedup vs baseline: 1.1515x; 1.1515x over previous
#include <cuda_runtime.h>
#include <cstdint>

#define BFc    116
#define HWs    3136
#define NBATCH 64
#define CTOT   232
#define EPSc   1e-5f
#define TTILE  7          // pixel tiles per block
#define NT     64         // pixels per tile

// ---------------- scratch ----------------
__device__ float g_h1[(size_t)NBATCH * BFc * HWs];
__device__ float g_h2[(size_t)NBATCH * BFc * HWs];
__device__ float g_wt1[128 * 128];   // fragment-packed (15360 used)
__device__ float g_wt2[128 * 128];
__device__ float g_sh1[128];
__device__ float g_sh2[128];

// ---------------- helpers ----------------
__device__ __forceinline__ float tf32r(float x) {
    uint32_t u;
    asm("cvt.rna.tf32.f32 %0, %1;" : "=r"(u) : "f"(x));
    return __uint_as_float(u);
}
__device__ __forceinline__ uint32_t smem_u32(const void* p) {
    uint32_t a;
    asm("{ .reg .u64 t; cvta.to.shared.u64 t, %1; cvt.u32.u64 %0, t; }" : "=r"(a) : "l"(p));
    return a;
}
__device__ __forceinline__ void cp_async16(uint32_t dst, const void* src) {
    asm volatile("cp.async.cg.shared.global [%0], [%1], 16;" :: "r"(dst), "l"(src));
}
#define CP_COMMIT() asm volatile("cp.async.commit_group;" ::: "memory")

__device__ __forceinline__ void mma_tf32(float* d, const uint32_t* a, const uint32_t* b) {
    asm volatile(
        "mma.sync.aligned.m16n8k8.row.col.f32.tf32.tf32.f32 "
        "{%0,%1,%2,%3}, {%4,%5,%6,%7}, {%8,%9}, {%0,%1,%2,%3};"
        : "+f"(d[0]), "+f"(d[1]), "+f"(d[2]), "+f"(d[3])
        : "r"(a[0]), "r"(a[1]), "r"(a[2]), "r"(a[3]), "r"(b[0]), "r"(b[1]));
}

// Fragment layout: Wf[((blk*15 + ks)*2 + mi)*128 + lane*4 + j]
//   gid = lane>>2, tig = lane&3
//   j0: (r, c)  j1: (r+8, c)  j2: (r, c+4)  j3: (r+8, c+4)
//   r = blk*32 + mi*16 + gid,  c = ks*8 + tig
#define WF_FLOATS (4 * 15 * 2 * 128)   // 15360

// ---------------- combined prep (fragment-packing) ----------------
__global__ void prep_all(const float* __restrict__ w2, const float* __restrict__ bn1g,
                         const float* __restrict__ bn1b, const float* __restrict__ bn1m,
                         const float* __restrict__ bn1v,
                         const float* __restrict__ w3,
                         const float* __restrict__ bn2g, const float* __restrict__ bn2b,
                         const float* __restrict__ bn2m, const float* __restrict__ bn2v,
                         const float* __restrict__ bn3g, const float* __restrict__ bn3b,
                         const float* __restrict__ bn3m, const float* __restrict__ bn3v,
                         float* __restrict__ wt1, float* __restrict__ sh1,
                         float* __restrict__ wt2, float* __restrict__ sh2) {
    if (blockIdx.x < 60) {
        // wt1: fragment-packed, bn1-scaled, tf32-rounded
        int i = blockIdx.x * 256 + threadIdx.x;   // 0..15359
        int j    = i & 3;
        int lane = (i >> 2) & 31;
        int mi   = (i >> 7) & 1;
        int t    = i >> 8;
        int ks   = t % 15;
        int blk  = t / 15;
        int gid = lane >> 2, tig = lane & 3;
        int r = blk * 32 + mi * 16 + gid + (j & 1) * 8;
        int c = ks * 8 + tig + ((j >> 1) & 1) * 4;
        float val = 0.f;
        if (r < BFc && c < BFc) {
            float s = bn1g[r] * rsqrtf(bn1v[r] + EPSc);
            val = tf32r(w2[r * BFc + c] * s);
        }
        wt1[i] = val;
        return;
    }
    if (blockIdx.x == 60) {
        int i = threadIdx.x;
        if (i < 128) {
            float shv = 0.f;
            if (i < BFc) {
                float s = bn1g[i] * rsqrtf(bn1v[i] + EPSc);
                shv = bn1b[i] - bn1m[i] * s;
            }
            sh1[i] = shv;
        }
        return;
    }
    // wt2 path: fold bn2 (input side) + bn3 (output side), fragment-packed
    __shared__ float s2s[BFc], t2s[BFc];
    int tid = threadIdx.x;
    if (tid < BFc) {
        float s2 = bn2g[tid] * rsqrtf(bn2v[tid] + EPSc);
        s2s[tid] = s2;
        t2s[tid] = bn2b[tid] - bn2m[tid] * s2;
    }
    __syncthreads();
    if (tid >= 128) return;
    int o = tid;
    float s3 = 0.f, t3 = 0.f;
    if (o < BFc) {
        s3 = bn3g[o] * rsqrtf(bn3v[o] + EPSc);
        t3 = bn3b[o] - bn3m[o] * s3;
    }
    // fragment-index components that depend only on o
    const int blk = o >> 5;
    const int rem = o & 31;
    const int mi = rem >> 4;
    const int r16 = rem & 15;
    const int gid = (r16 < 8) ? r16 : (r16 - 8);
    const int jbit0 = (r16 < 8) ? 0 : 1;
    float acc = 0.f;
    for (int k = 0; k < 120; k++) {
        float val = 0.f;
        if (o < BFc && k < BFc) {
            float wv = w3[o * BFc + k];
            val = tf32r(wv * s3 * s2s[k]);
            acc += wv * t2s[k];
        }
        int ks = k >> 3;
        int kc = k & 7;
        int tig = (kc < 4) ? kc : (kc - 4);
        int jbit1 = (kc < 4) ? 0 : 1;
        int lane = gid * 4 + tig;
        int idx = ((blk * 15 + ks) * 2 + mi) * 128 + lane * 4 + (jbit0 + 2 * jbit1);
        wt2[idx] = val;
    }
    sh2[o] = (o < BFc) ? (t3 + s3 * acc) : 0.f;
}

// ---------------- shuffle-copy: out[b][2k] = x[b][k] ----------------
__global__ void copy_x1_kernel(const float* __restrict__ x, float* __restrict__ out) {
    size_t i = (size_t)blockIdx.x * 256 + threadIdx.x;
    if (i >= (size_t)NBATCH * BFc * (HWs / 4)) return;
    int p4 = (int)(i % (HWs / 4));
    int bk = (int)(i / (HWs / 4));
    int k = bk % BFc;
    int b = bk / BFc;
    const float4* s = (const float4*)(x + ((size_t)b * CTOT + k) * HWs) + p4;
    float4* d = (float4*)(out + ((size_t)b * CTOT + 2 * k) * HWs) + p4;
    *d = *s;
}

// ---------------- split-K chunk-pipelined mma.sync tf32 fused 1x1 conv ----------------
#define XPITCH 72
#define KA_ROWS 56
#define KB_ROWS 64
#define SM_W   0
#define SM_XA  WF_FLOATS                      // 15360
#define SM_XB  (SM_XA + KA_ROWS * XPITCH)     // +4032
#define SM_S   (SM_XB + KB_ROWS * XPITCH)     // +4608
#define SMEM_FLOATS (SM_S + 128)              // 24128 floats = 96512 B

template<bool FIRST>
__global__ __launch_bounds__(256, 2)
void conv1x1_mma(const float* __restrict__ in, const float* __restrict__ wt,
                 const float* __restrict__ shifts, const float* __restrict__ alpha,
                 float* __restrict__ dst, int b0)
{
    extern __shared__ float smem[];
    float* Wsm = smem + SM_W;
    float* Ssm = smem + SM_S;

    const int tid = threadIdx.x;
    const int b = b0 + blockIdx.y;
    const int base = blockIdx.x * (TTILE * NT);

    const float* src_base = FIRST
        ? in + ((size_t)b * CTOT + BFc) * HWs + base
        : in + ((size_t)b * BFc) * HWs + base;

    const uint32_t xa = smem_u32(smem + SM_XA);
    const uint32_t xb = smem_u32(smem + SM_XB);

    for (int i = tid; i < 4 * XPITCH; i += 256)
        smem[SM_XB + 60 * XPITCH + i] = 0.f;

    for (int i = tid; i < KA_ROWS * 16; i += 256) {
        int k = i >> 4, q = i & 15;
        cp_async16(xa + (uint32_t)(k * XPITCH + q * 4) * 4,
                   src_base + (size_t)k * HWs + q * 4);
    }
    CP_COMMIT();
    for (int i = tid; i < 60 * 16; i += 256) {
        int k = i >> 4, q = i & 15;
        cp_async16(xb + (uint32_t)(k * XPITCH + q * 4) * 4,
                   src_base + (size_t)(KA_ROWS + k) * HWs + q * 4);
    }
    CP_COMMIT();

    // W fill: fragment-packed -> plain linear float4 copy
    {
        float4* wd = (float4*)Wsm;
        const float4* wsrc = (const float4*)wt;
        #pragma unroll 5
        for (int i = tid; i < WF_FLOATS / 4; i += 256) wd[i] = wsrc[i];
    }
    if (tid < 128) Ssm[tid] = shifts[tid];

    const int wid = tid >> 5, lane = tid & 31;
    const int gid = lane >> 2, tig = lane & 3;
    const int blk = wid >> 1;                 // A row-block 0..3
    const int pw = (wid & 1) * 32;
    const float al = __ldg(alpha);

    // per-thread A fragment base: Wsm + ((blk*15 + ks)*2 + mi)*128 + lane*4
    const float4* wfbase = (const float4*)Wsm + blk * 15 * 2 * 32 + lane;

    #pragma unroll 1
    for (int t = 0; t < TTILE; t++) {
        float acc[2][4][4];
        #pragma unroll
        for (int mi = 0; mi < 2; mi++)
            #pragma unroll
            for (int ni = 0; ni < 4; ni++)
                #pragma unroll
                for (int r = 0; r < 4; r++) acc[mi][ni][r] = 0.f;

        asm volatile("cp.async.wait_group 1;" ::: "memory");
        __syncthreads();

        #pragma unroll
        for (int ks = 0; ks < 7; ks++) {
            const int k0 = ks * 8;
            uint4 a[2];
            #pragma unroll
            for (int mi = 0; mi < 2; mi++)
                a[mi] = *(const uint4*)(wfbase + (ks * 2 + mi) * 32);
            uint32_t bf[4][2];
            #pragma unroll
            for (int ni = 0; ni < 4; ni++) {
                const float* xp = smem + SM_XA + (k0 + tig) * XPITCH + pw + ni * 8 + gid;
                bf[ni][0] = __float_as_uint(xp[0]);
                bf[ni][1] = __float_as_uint(xp[4 * XPITCH]);
            }
            #pragma unroll
            for (int mi = 0; mi < 2; mi++)
                #pragma unroll
                for (int ni = 0; ni < 4; ni++)
                    mma_tf32(acc[mi][ni], (const uint32_t*)&a[mi], bf[ni]);
        }

        __syncthreads();

        if (t + 1 < TTILE) {
            const float* src_t = src_base + (t + 1) * NT;
            for (int i = tid; i < KA_ROWS * 16; i += 256) {
                int k = i >> 4, q = i & 15;
                cp_async16(xa + (uint32_t)(k * XPITCH + q * 4) * 4,
                           src_t + (size_t)k * HWs + q * 4);
            }
            CP_COMMIT();
            asm volatile("cp.async.wait_group 1;" ::: "memory");
        } else {
            asm volatile("cp.async.wait_group 0;" ::: "memory");
        }
        __syncthreads();

        #pragma unroll
        for (int ks = 7; ks < 15; ks++) {
            const int k0 = (ks - 7) * 8;      // local row in chunk B
            uint4 a[2];
            #pragma unroll
            for (int mi = 0; mi < 2; mi++)
                a[mi] = *(const uint4*)(wfbase + (ks * 2 + mi) * 32);
            uint32_t bf[4][2];
            #pragma unroll
            for (int ni = 0; ni < 4; ni++) {
                const float* xp = smem + SM_XB + (k0 + tig) * XPITCH + pw + ni * 8 + gid;
                bf[ni][0] = __float_as_uint(xp[0]);
                bf[ni][1] = __float_as_uint(xp[4 * XPITCH]);
            }
            #pragma unroll
            for (int mi = 0; mi < 2; mi++)
                #pragma unroll
                for (int ni = 0; ni < 4; ni++)
                    mma_tf32(acc[mi][ni], (const uint32_t*)&a[mi], bf[ni]);
        }

        const int p0 = base + t * NT;
        #pragma unroll
        for (int mi = 0; mi < 2; mi++) {
            #pragma unroll
            for (int half = 0; half < 2; half++) {
                const int o = blk * 32 + mi * 16 + gid + half * 8;
                if (o < BFc) {
                    const float sh = Ssm[o];
                    float* dp = FIRST
                        ? dst + ((size_t)b * BFc + o) * HWs + p0
                        : dst + ((size_t)b * CTOT + 2 * o + 1) * HWs + p0;
                    #pragma unroll
                    for (int ni = 0; ni < 4; ni++) {
                        float c0 = acc[mi][ni][half * 2 + 0] + sh;
                        float c1 = acc[mi][ni][half * 2 + 1] + sh;
                        c0 = c0 >= 0.f ? c0 : al * c0;
                        c1 = c1 >= 0.f ? c1 : al * c1;
                        *(float2*)(dp + pw + ni * 8 + 2 * tig) = make_float2(c0, c1);
                    }
                }
            }
        }

        __syncthreads();

        if (t + 1 < TTILE) {
            const float* src_t = src_base + (t + 1) * NT;
            for (int i = tid; i < 60 * 16; i += 256) {
                int k = i >> 4, q = i & 15;
                cp_async16(xb + (uint32_t)(k * XPITCH + q * 4) * 4,
                           src_t + (size_t)(KA_ROWS + k) * HWs + q * 4);
            }
            CP_COMMIT();
        }
    }
}

// ---------------- depthwise 3x3, register-rolling, no smem, no barriers ----------------
__device__ __forceinline__ void dw_load_row(const float* __restrict__ src, int y,
                                            int x0, bool hasL, bool hasR, float* r) {
    if ((unsigned)y < 56u) {
        const float* p = src + y * 56 + x0;
        float4 c = *(const float4*)p;
        r[0] = hasL ? p[-1] : 0.f;
        r[1] = c.x; r[2] = c.y; r[3] = c.z; r[4] = c.w;
        r[5] = hasR ? p[4] : 0.f;
    } else {
        r[0] = r[1] = r[2] = r[3] = r[4] = r[5] = 0.f;
    }
}

__global__ __launch_bounds__(224)
void dwconv_kernel(const float* __restrict__ h1, const float* __restrict__ wdw,
                   float* __restrict__ h2, int plane0)
{
    const int tid = threadIdx.x;
    const int local = tid % 112;
    const int plane = plane0 + blockIdx.x * 2 + tid / 112;
    const int xg = local % 14;
    const int ys = local / 14;
    const int x0 = xg * 4;
    const int y0 = ys * 7;
    const bool hasL = (xg != 0);
    const bool hasR = (xg != 13);

    const int c = plane % BFc;
    const float* src = h1 + (size_t)plane * HWs;
    float* dstp = h2 + (size_t)plane * HWs + x0;

    float w[9];
    #pragma unroll
    for (int j = 0; j < 9; j++) w[j] = __ldg(wdw + c * 9 + j);

    float R[3][6];
    dw_load_row(src, y0 - 1, x0, hasL, hasR, R[0]);
    dw_load_row(src, y0,     x0, hasL, hasR, R[1]);

    #pragma unroll
    for (int j = 0; j < 7; j++) {
        dw_load_row(src, y0 + j + 1, x0, hasL, hasR, R[(j + 2) % 3]);
        const float* T = R[j % 3];
        const float* M = R[(j + 1) % 3];
        const float* B = R[(j + 2) % 3];
        float4 o;
        o.x = w[0]*T[0] + w[1]*T[1] + w[2]*T[2]
            + w[3]*M[0] + w[4]*M[1] + w[5]*M[2]
            + w[6]*B[0] + w[7]*B[1] + w[8]*B[2];
        o.y = w[0]*T[1] + w[1]*T[2] + w[2]*T[3]
            + w[3]*M[1] + w[4]*M[2] + w[5]*M[3]
            + w[6]*B[1] + w[7]*B[2] + w[8]*B[3];
        o.z = w[0]*T[2] + w[1]*T[3] + w[2]*T[4]
            + w[3]*M[2] + w[4]*M[3] + w[5]*M[4]
            + w[6]*B[2] + w[7]*B[3] + w[8]*B[4];
        o.w = w[0]*T[3] + w[1]*T[4] + w[2]*T[5]
            + w[3]*M[3] + w[4]*M[4] + w[5]*M[5]
            + w[6]*B[3] + w[7]*B[4] + w[8]*B[5];
        *(float4*)(dstp + (y0 + j) * 56) = o;
    }
}

// ---------------- launch: round-12 forked graph (copy ∥ twin half-batch chains) ----------------
extern "C" void kernel_launch(void* const* d_in, const int* in_sizes, int n_in,
                              void* d_out, int out_size) {
    const float* x      = (const float*)d_in[0];
    const float* w2     = (const float*)d_in[1];
    const float* bn1_g  = (const float*)d_in[2];
    const float* bn1_b  = (const float*)d_in[3];
    const float* bn1_m  = (const float*)d_in[4];
    const float* bn1_v  = (const float*)d_in[5];
    const float* alpha1 = (const float*)d_in[6];
    const float* wdw    = (const float*)d_in[7];
    const float* bn2_g  = (const float*)d_in[8];
    const float* bn2_b  = (const float*)d_in[9];
    const float* bn2_m  = (const float*)d_in[10];
    const float* bn2_v  = (const float*)d_in[11];
    const float* w3     = (const float*)d_in[12];
    const float* bn3_g  = (const float*)d_in[13];
    const float* bn3_b  = (const float*)d_in[14];
    const float* bn3_m  = (const float*)d_in[15];
    const float* bn3_v  = (const float*)d_in[16];
    const float* alpha2 = (const float*)d_in[17];
    float* out = (float*)d_out;

    float *h1, *h2, *wt1, *wt2, *sh1, *sh2;
    cudaGetSymbolAddress((void**)&h1,  g_h1);
    cudaGetSymbolAddress((void**)&h2,  g_h2);
    cudaGetSymbolAddress((void**)&wt1, g_wt1);
    cudaGetSymbolAddress((void**)&wt2, g_wt2);
    cudaGetSymbolAddress((void**)&sh1, g_sh1);
    cudaGetSymbolAddress((void**)&sh2, g_sh2);

    const int smem_bytes = SMEM_FLOATS * 4;   // 96512 B -> 2 CTAs/SM
    cudaFuncSetAttribute(conv1x1_mma<true>,
                         cudaFuncAttributeMaxDynamicSharedMemorySize, smem_bytes);
    cudaFuncSetAttribute(conv1x1_mma<false>,
                         cudaFuncAttributeMaxDynamicSharedMemorySize, smem_bytes);

    static bool inited = false;
    static cudaStream_t s1, s2;
    static cudaEvent_t e0, eP, e1, e2;
    if (!inited) {
        cudaStreamCreateWithFlags(&s1, cudaStreamNonBlocking);
        cudaStreamCreateWithFlags(&s2, cudaStreamNonBlocking);
        cudaEventCreateWithFlags(&e0, cudaEventDisableTiming);
        cudaEventCreateWithFlags(&eP, cudaEventDisableTiming);
        cudaEventCreateWithFlags(&e1, cudaEventDisableTiming);
        cudaEventCreateWithFlags(&e2, cudaEventDisableTiming);
        inited = true;
    }

    const int HB = NBATCH / 2;   // 32 batches per chain

    // fork root
    cudaEventRecord(e0, 0);

    // branch s1: independent shuffle-copy (even output channels)
    cudaStreamWaitEvent(s1, e0, 0);
    {
        size_t n4 = (size_t)NBATCH * BFc * (HWs / 4);
        copy_x1_kernel<<<(unsigned)((n4 + 255) / 256), 256, 0, s1>>>(x, out);
    }
    cudaEventRecord(e1, s1);

    // default stream: prep, then chain A (b 0..31)
    prep_all<<<62, 256>>>(w2, bn1_g, bn1_b, bn1_m, bn1_v,
                          w3, bn2_g, bn2_b, bn2_m, bn2_v,
                          bn3_g, bn3_b, bn3_m, bn3_v,
                          wt1, sh1, wt2, sh2);
    cudaEventRecord(eP, 0);

    // branch s2: chain B (b 32..63), gated on prep
    cudaStreamWaitEvent(s2, eP, 0);

    conv1x1_mma<true><<<dim3(TTILE, HB), 256, smem_bytes>>>(x, wt1, sh1, alpha1, h1, 0);
    conv1x1_mma<true><<<dim3(TTILE, HB), 256, smem_bytes, s2>>>(x, wt1, sh1, alpha1, h1, HB);

    dwconv_kernel<<<(HB * BFc) / 2, 224>>>(h1, wdw, h2, 0);
    dwconv_kernel<<<(HB * BFc) / 2, 224, 0, s2>>>(h1, wdw, h2, HB * BFc);

    conv1x1_mma<false><<<dim3(TTILE, HB), 256, smem_bytes>>>(h2, wt2, sh2, alpha2, out, 0);
    conv1x1_mma<false><<<dim3(TTILE, HB), 256, smem_bytes, s2>>>(h2, wt2, sh2, alpha2, out, HB);
    cudaEventRecord(e2, s2);

    // join both branches back into the default stream
    cudaStreamWaitEvent(0, e1, 0);
    cudaStreamWaitEvent(0, e2, 0);
}